// round 11
// baseline (speedup 1.0000x reference)
#include <cuda_runtime.h>
#include <cstdint>

// Depthwise1d: out[n,c,o] = sum_i x[n,c,i] * W[c,o,i] + b[c,o]
// N=4096, C=256, K=64, O=128, fp32.
//
// R10: R6 compute tile (col-pair FFMA2, r=8 x c=8) but x is read DIRECTLY
// from global through L1 (16-way broadcast reuse -> L1-resident), removing
// the x staging pass and its barrier. W stays in smem (staged once/CTA,
// pre-transposed k-major by helper kernel). One __syncthreads per block.

#define N_TOT   4096
#define C_TOT   256
#define K_IN    64
#define O_OUT   128
#define TILE_M  128
#define THREADS 256
#define WSTR    132      // Wsh k-row stride (floats)

// 8 MB scratch: W2g[c][k][o]
__device__ float W2g[C_TOT * K_IN * O_OUT];

__device__ __forceinline__ void ffma2(unsigned long long& d,
                                      unsigned long long a,
                                      unsigned long long b) {
    asm("fma.rn.f32x2 %0, %1, %2, %0;" : "+l"(d) : "l"(a), "l"(b));
}
__device__ __forceinline__ unsigned long long dup2(float w) {
    unsigned long long r;
    asm("mov.b64 %0, {%1, %1};" : "=l"(r) : "f"(w));
    return r;
}
__device__ __forceinline__ float2 unpack2(unsigned long long v) {
    float2 f;
    asm("mov.b64 {%0, %1}, %2;" : "=f"(f.x), "=f"(f.y) : "l"(v));
    return f;
}

// ---- Kernel A: W[c][o][k] -> W2g[c][k][o] (tiny) ----
__global__ __launch_bounds__(256)
void w_transpose(const float* __restrict__ W) {
    __shared__ float Wt[O_OUT * 68];
    const int t = threadIdx.x;
    const int c = blockIdx.x;
#pragma unroll
    for (int j = 0; j < 8; ++j) {
        int idx = t + 256 * j;
        int o = idx >> 4, q = idx & 15;
        float4 v = *(const float4*)(W + ((size_t)c * O_OUT + o) * K_IN + 4 * q);
        *(float4*)&Wt[o * 68 + 4 * q] = v;
    }
    __syncthreads();
    float* dst = W2g + (size_t)c * K_IN * O_OUT;
#pragma unroll
    for (int j = 0; j < 32; ++j) {
        int idx = t + 256 * j;
        int k = idx >> 7, o = idx & 127;
        dst[k * O_OUT + o] = Wt[o * 68 + k];
    }
}

// ---- Kernel B: main GEMM ----
__global__ __launch_bounds__(THREADS, 2)
void dw1d_kernel(const float* __restrict__ x,
                 const float* __restrict__ b,
                 float* __restrict__ out) {
    extern __shared__ float smem[];
    float* Wsh = smem;                       // [k][o] stride WSTR

    const int t  = threadIdx.x;
    const int cg = t & 15;
    const int rg = t >> 4;
    const int n0 = blockIdx.x * TILE_M;
    const int c  = blockIdx.y;

    // stage W (k-major): coalesced LDG.128 -> Wsh[k][o]; the only barrier.
    {
        const float* wb = W2g + (size_t)c * K_IN * O_OUT;
#pragma unroll
        for (int j = 0; j < 8; ++j) {
            int idx = t + THREADS * j;       // 0..2047
            int k = idx >> 5, o4 = idx & 31;
            float4 v = *(const float4*)(wb + k * O_OUT + 4 * o4);
            *(float4*)&Wsh[k * WSTR + 4 * o4] = v;
        }
    }
    __syncthreads();

    // compute: rows r_i = rg + 16*i (i<8); cols {4cg..+3, 64+4cg..+3}
    unsigned long long acc[8][4];
#pragma unroll
    for (int i = 0; i < 8; ++i)
#pragma unroll
        for (int j = 0; j < 4; ++j)
            acc[i][j] = 0ULL;

    const float* wrow0 = &Wsh[4 * cg];
    const float* wrow1 = &Wsh[4 * cg + 64];

    // x row base for this thread's row group; rows at +i*16 rows
    const float* xbase = x + ((size_t)(n0 + rg) * C_TOT + c) * K_IN;
    const size_t RSTR = (size_t)16 * C_TOT * K_IN;   // 16 rows in floats

#pragma unroll 4
    for (int k2 = 0; k2 < K_IN / 2; ++k2) {
        // x: k-pair LDG.64 per row, 2 addresses/warp, L1-resident after 1st touch
        float2 xp[8];
#pragma unroll
        for (int i = 0; i < 8; ++i)
            xp[i] = __ldg((const float2*)(xbase + i * RSTR + 2 * k2));

        ulonglong2 wa0 = *(const ulonglong2*)(wrow0 + (2 * k2) * WSTR);
        ulonglong2 wa1 = *(const ulonglong2*)(wrow1 + (2 * k2) * WSTR);
        ulonglong2 wb0 = *(const ulonglong2*)(wrow0 + (2 * k2 + 1) * WSTR);
        ulonglong2 wb1 = *(const ulonglong2*)(wrow1 + (2 * k2 + 1) * WSTR);

#pragma unroll
        for (int i = 0; i < 8; ++i) {
            unsigned long long x0 = dup2(xp[i].x);
            unsigned long long x1 = dup2(xp[i].y);
            ffma2(acc[i][0], x0, wa0.x);
            ffma2(acc[i][1], x0, wa0.y);
            ffma2(acc[i][2], x0, wa1.x);
            ffma2(acc[i][3], x0, wa1.y);
            ffma2(acc[i][0], x1, wb0.x);
            ffma2(acc[i][1], x1, wb0.y);
            ffma2(acc[i][2], x1, wb1.x);
            ffma2(acc[i][3], x1, wb1.y);
        }
    }

    // epilogue: bias via __ldg (L2-hot), 2 coalesced STG.128 per row
    const float4 b0 = __ldg((const float4*)(b + c * O_OUT + 4 * cg));
    const float4 b1 = __ldg((const float4*)(b + c * O_OUT + 64 + 4 * cg));

#pragma unroll
    for (int i = 0; i < 8; ++i) {
        int n = n0 + rg + 16 * i;
        float* orow = out + ((size_t)n * C_TOT + c) * O_OUT;
        float2 p0 = unpack2(acc[i][0]);
        float2 p1 = unpack2(acc[i][1]);
        float2 p2 = unpack2(acc[i][2]);
        float2 p3 = unpack2(acc[i][3]);
        float4 v0 = make_float4(p0.x + b0.x, p0.y + b0.y, p1.x + b0.z, p1.y + b0.w);
        float4 v1 = make_float4(p2.x + b1.x, p2.y + b1.y, p3.x + b1.z, p3.y + b1.w);
        *(float4*)&orow[4 * cg]      = v0;
        *(float4*)&orow[64 + 4 * cg] = v1;
    }
}

extern "C" void kernel_launch(void* const* d_in, const int* in_sizes, int n_in,
                              void* d_out, int out_size) {
    const float* x = (const float*)d_in[0];
    const float* W = (const float*)d_in[1];
    const float* b = (const float*)d_in[2];
    float* out = (float*)d_out;

    w_transpose<<<C_TOT, 256>>>(W);

    size_t smem_bytes = (size_t)(K_IN * WSTR) * sizeof(float);  // 33792
    cudaFuncSetAttribute(dw1d_kernel,
                         cudaFuncAttributeMaxDynamicSharedMemorySize,
                         (int)smem_bytes);
    dim3 grid(N_TOT / TILE_M, C_TOT);
    dw1d_kernel<<<grid, THREADS, smem_bytes>>>(x, b, out);
}

// round 13
// speedup vs baseline: 1.2158x; 1.2158x over previous
#include <cuda_runtime.h>
#include <cstdint>

// Depthwise1d: out[n,c,o] = sum_i x[n,c,i] * W[c,o,i] + b[c,o]
// N=4096, C=256, K=64, O=128, fp32.
//
// R11: R6's validated inner tile (x LDS.32 broadcast + W LDS.128, col-pair
// FFMA2, r=8 x c=8) with 2 m-tiles per CTA and cp.async double-buffered X
// at COMPILE-TIME-FIXED smem offsets (no dynamic indexing -> no alu bloat).
// W staged once per CTA (amortized over both tiles).

#define N_TOT   4096
#define C_TOT   256
#define K_IN    64
#define O_OUT   128
#define TILE_M  128
#define THREADS 256
#define XSTR    68       // X buffer row stride (floats)
#define WSTR    132      // Wsh k-row stride (floats)

#define WOFF    (K_IN * WSTR)            // 8448 floats = 33792 B
#define XBUF_FL (TILE_M * XSTR)          // 8704 floats = 34816 B
#define SMEM_FL (WOFF + 2 * XBUF_FL)     // 25856 floats = 103424 B

// 8 MB scratch: W2g[c][k][o]
__device__ float W2g[C_TOT * K_IN * O_OUT];

__device__ __forceinline__ void ffma2(unsigned long long& d,
                                      unsigned long long a,
                                      unsigned long long b) {
    asm("fma.rn.f32x2 %0, %1, %2, %0;" : "+l"(d) : "l"(a), "l"(b));
}
__device__ __forceinline__ unsigned long long dup2(float w) {
    unsigned long long r;
    asm("mov.b64 %0, {%1, %1};" : "=l"(r) : "f"(w));
    return r;
}
__device__ __forceinline__ float2 unpack2(unsigned long long v) {
    float2 f;
    asm("mov.b64 {%0, %1}, %2;" : "=f"(f.x), "=f"(f.y) : "l"(v));
    return f;
}
__device__ __forceinline__ uint32_t smem_u32(const void* p) {
    uint32_t a;
    asm("{ .reg .u64 t; cvta.to.shared.u64 t, %1; cvt.u32.u64 %0, t; }" : "=r"(a) : "l"(p));
    return a;
}
__device__ __forceinline__ void cp_async16(uint32_t dst, const void* src) {
    asm volatile("cp.async.cg.shared.global [%0], [%1], 16;" :: "r"(dst), "l"(src));
}
#define CP_COMMIT() asm volatile("cp.async.commit_group;" ::: "memory")
#define CP_WAIT(n)  asm volatile("cp.async.wait_group %0;" :: "n"(n) : "memory")

// ---- Kernel A: W[c][o][k] -> W2g[c][k][o] (tiny) ----
__global__ __launch_bounds__(256)
void w_transpose(const float* __restrict__ W) {
    __shared__ float Wt[O_OUT * 68];
    const int t = threadIdx.x;
    const int c = blockIdx.x;
#pragma unroll
    for (int j = 0; j < 8; ++j) {
        int idx = t + 256 * j;
        int o = idx >> 4, q = idx & 15;
        float4 v = *(const float4*)(W + ((size_t)c * O_OUT + o) * K_IN + 4 * q);
        *(float4*)&Wt[o * 68 + 4 * q] = v;
    }
    __syncthreads();
    float* dst = W2g + (size_t)c * K_IN * O_OUT;
#pragma unroll
    for (int j = 0; j < 32; ++j) {
        int idx = t + 256 * j;
        int k = idx >> 7, o = idx & 127;
        dst[k * O_OUT + o] = Wt[o * 68 + k];
    }
}

// X prefetch for one m-tile into buffer at static smem offset (cp.async)
__device__ __forceinline__ void prefetch_x(const float* __restrict__ xb,
                                           int n0, uint32_t sbase, int t) {
#pragma unroll
    for (int j = 0; j < 8; ++j) {
        int idx = t + THREADS * j;           // 0..2047
        int row = idx >> 4, ku = idx & 15;
        const void* src = xb + (size_t)(n0 + row) * C_TOT * K_IN + 4 * ku;
        cp_async16(sbase + (uint32_t)((row * XSTR + 4 * ku) * 4), src);
    }
}

// R6 compute tile + epilogue for one m-tile (Xsh at compile-time offset)
__device__ __forceinline__ void compute_tile(const float* __restrict__ Xsh,
                                             const float* __restrict__ wrow0,
                                             const float* __restrict__ wrow1,
                                             float4 b0, float4 b1,
                                             float* __restrict__ out,
                                             int n0, int c, int cg, int rg) {
    unsigned long long acc[8][4];
#pragma unroll
    for (int i = 0; i < 8; ++i)
#pragma unroll
        for (int j = 0; j < 4; ++j)
            acc[i][j] = 0ULL;

#pragma unroll 4
    for (int k = 0; k < K_IN; ++k) {
        float xs[8];
#pragma unroll
        for (int i = 0; i < 8; ++i)
            xs[i] = Xsh[(rg + 16 * i) * XSTR + k];   // broadcast LDS.32

        ulonglong2 wv0 = *(const ulonglong2*)(wrow0 + k * WSTR);
        ulonglong2 wv1 = *(const ulonglong2*)(wrow1 + k * WSTR);
#pragma unroll
        for (int i = 0; i < 8; ++i) {
            unsigned long long xd = dup2(xs[i]);
            ffma2(acc[i][0], xd, wv0.x);
            ffma2(acc[i][1], xd, wv0.y);
            ffma2(acc[i][2], xd, wv1.x);
            ffma2(acc[i][3], xd, wv1.y);
        }
    }

#pragma unroll
    for (int i = 0; i < 8; ++i) {
        int n = n0 + rg + 16 * i;
        float* orow = out + ((size_t)n * C_TOT + c) * O_OUT;
        float2 p0 = unpack2(acc[i][0]);
        float2 p1 = unpack2(acc[i][1]);
        float2 p2 = unpack2(acc[i][2]);
        float2 p3 = unpack2(acc[i][3]);
        float4 v0 = make_float4(p0.x + b0.x, p0.y + b0.y, p1.x + b0.z, p1.y + b0.w);
        float4 v1 = make_float4(p2.x + b1.x, p2.y + b1.y, p3.x + b1.z, p3.y + b1.w);
        *(float4*)&orow[4 * cg]      = v0;
        *(float4*)&orow[64 + 4 * cg] = v1;
    }
}

// ---- Kernel B: main GEMM, 2 m-tiles per CTA, double-buffered X ----
__global__ __launch_bounds__(THREADS, 2)
void dw1d_kernel(const float* __restrict__ x,
                 const float* __restrict__ b,
                 float* __restrict__ out) {
    extern __shared__ float smem[];
    float* Wsh = smem;                        // [k][o] stride WSTR
    const float* X0 = smem + WOFF;            // tile 0 buffer (static)
    const float* X1 = smem + WOFF + XBUF_FL;  // tile 1 buffer (static)

    const int t  = threadIdx.x;
    const int cg = t & 15;
    const int rg = t >> 4;
    const int c  = blockIdx.y;
    const int n0 = blockIdx.x * (2 * TILE_M); // tiles at n0 and n0+TILE_M

    const float* xb = x + (size_t)c * K_IN;
    const uint32_t sb32 = smem_u32(smem);

    // prefetch X0, then stage W (overlaps X0 flight), then prefetch X1
    prefetch_x(xb, n0, sb32 + WOFF * 4, t);
    CP_COMMIT();

    {
        const float* wb = W2g + (size_t)c * K_IN * O_OUT;
#pragma unroll
        for (int j = 0; j < 8; ++j) {
            int idx = t + THREADS * j;
            int k = idx >> 5, o4 = idx & 31;
            float4 v = *(const float4*)(wb + k * O_OUT + 4 * o4);
            *(float4*)&Wsh[k * WSTR + 4 * o4] = v;
        }
    }

    prefetch_x(xb, n0 + TILE_M, sb32 + (WOFF + XBUF_FL) * 4, t);
    CP_COMMIT();

    const float* wrow0 = &Wsh[4 * cg];
    const float* wrow1 = &Wsh[4 * cg + 64];
    const float4 b0 = __ldg((const float4*)(b + c * O_OUT + 4 * cg));
    const float4 b1 = __ldg((const float4*)(b + c * O_OUT + 64 + 4 * cg));

    CP_WAIT(1);                               // X0 landed (X1 still in flight)
    __syncthreads();
    compute_tile(X0, wrow0, wrow1, b0, b1, out, n0, c, cg, rg);

    CP_WAIT(0);                               // X1 landed
    __syncthreads();
    compute_tile(X1, wrow0, wrow1, b0, b1, out, n0 + TILE_M, c, cg, rg);
}

extern "C" void kernel_launch(void* const* d_in, const int* in_sizes, int n_in,
                              void* d_out, int out_size) {
    const float* x = (const float*)d_in[0];
    const float* W = (const float*)d_in[1];
    const float* b = (const float*)d_in[2];
    float* out = (float*)d_out;

    w_transpose<<<C_TOT, 256>>>(W);

    size_t smem_bytes = (size_t)SMEM_FL * sizeof(float);   // 103424
    cudaFuncSetAttribute(dw1d_kernel,
                         cudaFuncAttributeMaxDynamicSharedMemorySize,
                         (int)smem_bytes);
    dim3 grid(N_TOT / (2 * TILE_M), C_TOT);
    dw1d_kernel<<<grid, THREADS, smem_bytes>>>(x, b, out);
}